// round 1
// baseline (speedup 1.0000x reference)
#include <cuda_runtime.h>
#include <math.h>

#define BATCH   1024
#define SDIM    2048
#define N_ITER  16
#define PITERS  72

#define BM 128
#define BN 128
#define BK 16
#define TM 8
#define TN 8
#define NT 256

// ---------------- static device scratch (no allocations allowed) ----------------
__device__ __align__(256) float g_yth[BATCH * SDIM];
__device__ __align__(256) float g_ydl[BATCH * SDIM];
__device__ __align__(256) float g_xth[BATCH * SDIM];
__device__ __align__(256) float g_xdl[BATCH * SDIM];
__device__ __align__(256) float g_u  [BATCH * SDIM];
__device__ __align__(256) float g_res[BATCH * SDIM];
__device__ __align__(256) float g_MA [SDIM * SDIM];
__device__ __align__(256) float g_MB [SDIM * SDIM];
__device__ __align__(256) float g_vec [SDIM];
__device__ __align__(256) float g_wvec[SDIM];
__device__ float g_scal[4];   // [0] = 1/L, [1] = thresh = alpha/(2L)

__device__ __forceinline__ float softthr(float v, float th) {
    float a = fabsf(v) - th;
    return a > 0.0f ? copysignf(a, v) : 0.0f;
}

// ---------------------------------------------------------------------------
// C[m,n] = sum_k opA(A)[m,k] * opB(B)[k,n],  K = SDIM always.
// TRA=0: A[m*lda+k] (k-contig)   TRA=1: A[k*lda+m] (m-contig)
// TRB=0: B[k*ldb+n] (n-contig)   TRB=1: B[n*ldb+k] (k-contig)
// EPI=0: C[m*SDIM+n] = acc                         (eigen-chain GEMMs)
// EPI=1: res = Y - src*acc - ydl ; u = src*res     (GEMM1 of FISTA step)
// EPI=2: full FISTA update for theta (acc) and delta (res), optional d_out
// ---------------------------------------------------------------------------
template<int TRA, int TRB, int EPI>
__global__ void __launch_bounds__(NT)
gemm_kernel(const float* __restrict__ A, int lda,
            const float* __restrict__ Bm, int ldb,
            float* __restrict__ C,
            const float* __restrict__ src, const float* __restrict__ Yg,
            float* __restrict__ resv, float* __restrict__ uv,
            float* __restrict__ xth, float* __restrict__ yth,
            float* __restrict__ xdl, float* __restrict__ ydl,
            float* __restrict__ outp, float mom)
{
    __shared__ float As[BK][BM + 4];
    __shared__ float Bs[BK][BN + 4];
    const int tid  = threadIdx.x;
    const int tx   = tid & 15;
    const int ty   = tid >> 4;
    const int row0 = blockIdx.y * BM;
    const int col0 = blockIdx.x * BN;

    float acc[TM][TN];
#pragma unroll
    for (int i = 0; i < TM; i++)
#pragma unroll
        for (int j = 0; j < TN; j++) acc[i][j] = 0.0f;

    for (int kt = 0; kt < SDIM; kt += BK) {
        if (TRA == 0) {
#pragma unroll
            for (int i = 0; i < 2; i++) {
                int v = tid + i * NT;
                int r = v >> 2, kq = (v & 3) << 2;
                float4 t = *reinterpret_cast<const float4*>(
                    &A[(size_t)(row0 + r) * lda + kt + kq]);
                As[kq + 0][r] = t.x; As[kq + 1][r] = t.y;
                As[kq + 2][r] = t.z; As[kq + 3][r] = t.w;
            }
        } else {
#pragma unroll
            for (int i = 0; i < 2; i++) {
                int v = tid + i * NT;
                int k = v >> 5, mq = (v & 31) << 2;
                float4 t = *reinterpret_cast<const float4*>(
                    &A[(size_t)(kt + k) * lda + row0 + mq]);
                *reinterpret_cast<float4*>(&As[k][mq]) = t;
            }
        }
        if (TRB == 0) {
#pragma unroll
            for (int i = 0; i < 2; i++) {
                int v = tid + i * NT;
                int k = v >> 5, nq = (v & 31) << 2;
                float4 t = *reinterpret_cast<const float4*>(
                    &Bm[(size_t)(kt + k) * ldb + col0 + nq]);
                *reinterpret_cast<float4*>(&Bs[k][nq]) = t;
            }
        } else {
#pragma unroll
            for (int i = 0; i < 2; i++) {
                int v = tid + i * NT;
                int n = v >> 2, kq = (v & 3) << 2;
                float4 t = *reinterpret_cast<const float4*>(
                    &Bm[(size_t)(col0 + n) * ldb + kt + kq]);
                Bs[kq + 0][n] = t.x; Bs[kq + 1][n] = t.y;
                Bs[kq + 2][n] = t.z; Bs[kq + 3][n] = t.w;
            }
        }
        __syncthreads();
#pragma unroll
        for (int k = 0; k < BK; k++) {
            float a[TM], b[TN];
            *reinterpret_cast<float4*>(&a[0]) = *reinterpret_cast<const float4*>(&As[k][ty * TM]);
            *reinterpret_cast<float4*>(&a[4]) = *reinterpret_cast<const float4*>(&As[k][ty * TM + 4]);
            *reinterpret_cast<float4*>(&b[0]) = *reinterpret_cast<const float4*>(&Bs[k][tx * TN]);
            *reinterpret_cast<float4*>(&b[4]) = *reinterpret_cast<const float4*>(&Bs[k][tx * TN + 4]);
#pragma unroll
            for (int i = 0; i < TM; i++)
#pragma unroll
                for (int j = 0; j < TN; j++)
                    acc[i][j] += a[i] * b[j];
        }
        __syncthreads();
    }

    if (EPI == 0) {
#pragma unroll
        for (int i = 0; i < TM; i++) {
            int m = row0 + ty * TM + i;
#pragma unroll
            for (int j = 0; j < TN; j++)
                C[(size_t)m * SDIM + col0 + tx * TN + j] = acc[i][j];
        }
    } else if (EPI == 1) {
#pragma unroll
        for (int i = 0; i < TM; i++) {
            int m = row0 + ty * TM + i;
#pragma unroll
            for (int j = 0; j < TN; j++) {
                int idx = m * SDIM + col0 + tx * TN + j;
                float s = src[idx];
                float r = Yg[idx] - s * acc[i][j] - ydl[idx];
                resv[idx] = r;
                uv[idx]   = s * r;
            }
        }
    } else {
        const float invL = g_scal[0];
        const float th   = g_scal[1];
#pragma unroll
        for (int i = 0; i < TM; i++) {
            int m = row0 + ty * TM + i;
#pragma unroll
            for (int j = 0; j < TN; j++) {
                int n   = col0 + tx * TN + j;
                int idx = m * SDIM + n;
                // theta half
                float vt  = yth[idx] + acc[i][j] * invL;
                float xnt = softthr(vt, th);
                float ynt = xnt + mom * (xnt - xth[idx]);
                xth[idx] = xnt; yth[idx] = ynt;
                // delta half (pure elementwise, fused here)
                float vd  = ydl[idx] + resv[idx] * invL;
                float xnd = softthr(vd, th);
                float ynd = xnd + mom * (xnd - xdl[idx]);
                xdl[idx] = xnd; ydl[idx] = ynd;
                if (outp) {
                    outp[(size_t)m * (2 * SDIM) + n]        = xnt;
                    outp[(size_t)m * (2 * SDIM) + SDIM + n] = xnd;
                }
            }
        }
    }
}

// ---------------- eigen-path helper kernels ----------------
__global__ void fill_kernel() {
    int i = blockIdx.x * blockDim.x + threadIdx.x;
    if (i < SDIM) {
        unsigned h = (unsigned)i * 2654435761u;
        h ^= h >> 13; h *= 2246822519u; h ^= h >> 16;
        g_vec[i] = (float)(h & 0xFFFF) / 65536.0f - 0.5f;
    }
}

__global__ void matvec_kernel(const float* __restrict__ H,
                              const float* __restrict__ x,
                              float* __restrict__ y) {
    int row = blockIdx.x;
    const float* hr = H + (size_t)row * SDIM;
    float s = 0.0f;
    for (int j = threadIdx.x; j < SDIM; j += 256) s += hr[j] * x[j];
#pragma unroll
    for (int o = 16; o > 0; o >>= 1) s += __shfl_xor_sync(0xffffffffu, s, o);
    __shared__ float part[8];
    int wid = threadIdx.x >> 5;
    if ((threadIdx.x & 31) == 0) part[wid] = s;
    __syncthreads();
    if (threadIdx.x == 0) {
        float t = 0.0f;
#pragma unroll
        for (int w = 0; w < 8; w++) t += part[w];
        y[row] = t;
    }
}

// Normalizes w into v. Pre-scales by 2^-32 so ||w||^2 can't overflow fp32
// (entries of G^32 * v reach ~1e18).
__global__ void normalize_kernel(const float* __restrict__ w, float* __restrict__ v) {
    const float sc = 2.3283064365386963e-10f;   // 2^-32
    float ss = 0.0f;
    for (int i = threadIdx.x; i < SDIM; i += 256) { float t = w[i] * sc; ss += t * t; }
#pragma unroll
    for (int o = 16; o > 0; o >>= 1) ss += __shfl_xor_sync(0xffffffffu, ss, o);
    __shared__ float part[8];
    __shared__ float s_inv;
    int wid = threadIdx.x >> 5;
    if ((threadIdx.x & 31) == 0) part[wid] = ss;
    __syncthreads();
    if (threadIdx.x == 0) {
        float t = 0.0f;
        for (int i = 0; i < 8; i++) t += part[i];
        s_inv = rsqrtf(t) * sc;   // = 1/||w||
    }
    __syncthreads();
    float inv = s_inv;
    for (int i = threadIdx.x; i < SDIM; i += 256) v[i] = w[i] * inv;
}

// lam32 = (v.w)/(v.v) with w = G^32 v  ->  L = lam32^(1/32); writes 1/L, thresh.
__global__ void finalize_kernel(const float* __restrict__ v,
                                const float* __restrict__ w,
                                const float* __restrict__ alpha) {
    float num = 0.0f, den = 0.0f;
    for (int i = threadIdx.x; i < SDIM; i += 256) { num += v[i] * w[i]; den += v[i] * v[i]; }
#pragma unroll
    for (int o = 16; o > 0; o >>= 1) {
        num += __shfl_xor_sync(0xffffffffu, num, o);
        den += __shfl_xor_sync(0xffffffffu, den, o);
    }
    __shared__ float pn[8], pd[8];
    int wid = threadIdx.x >> 5;
    if ((threadIdx.x & 31) == 0) { pn[wid] = num; pd[wid] = den; }
    __syncthreads();
    if (threadIdx.x == 0) {
        double n = 0.0, d = 0.0;
        for (int i = 0; i < 8; i++) { n += pn[i]; d += pd[i]; }
        double lam32 = n / d;
        double L = pow(lam32, 1.0 / 32.0);
        g_scal[0] = (float)(1.0 / L);
        g_scal[1] = (float)((double)alpha[0] * 0.5 / L);
    }
}

#define GEMM_NULLS nullptr, nullptr, nullptr, nullptr, nullptr, nullptr, nullptr, nullptr, nullptr, 0.0f

extern "C" void kernel_launch(void* const* d_in, const int* in_sizes, int n_in,
                              void* d_out, int out_size) {
    (void)in_sizes; (void)n_in; (void)out_size;
    const float* src   = (const float*)d_in[0];
    const float* Y     = (const float*)d_in[1];
    const float* W     = (const float*)d_in[2];
    const float* alpha = (const float*)d_in[3];
    float* out = (float*)d_out;

    float *yth, *ydl, *xth, *xdl, *u, *res, *MA, *MB, *vec, *wvec;
    cudaGetSymbolAddress((void**)&yth,  g_yth);
    cudaGetSymbolAddress((void**)&ydl,  g_ydl);
    cudaGetSymbolAddress((void**)&xth,  g_xth);
    cudaGetSymbolAddress((void**)&xdl,  g_xdl);
    cudaGetSymbolAddress((void**)&u,    g_u);
    cudaGetSymbolAddress((void**)&res,  g_res);
    cudaGetSymbolAddress((void**)&MA,   g_MA);
    cudaGetSymbolAddress((void**)&MB,   g_MB);
    cudaGetSymbolAddress((void**)&vec,  g_vec);
    cudaGetSymbolAddress((void**)&wvec, g_wvec);

    dim3 gridE(SDIM / BN, SDIM / BM);    // 16 x 16
    dim3 gridM(SDIM / BN, BATCH / BM);   // 16 x 8

    // ---- L = lambda_max(W^T W): G, then 5 squarings -> G^32, then power iter ----
    gemm_kernel<1, 0, 0><<<gridE, NT>>>(W,  SDIM, W,  SDIM, MA, GEMM_NULLS);   // MA = W^T W
    gemm_kernel<0, 0, 0><<<gridE, NT>>>(MA, SDIM, MA, SDIM, MB, GEMM_NULLS);   // MB = G^2
    gemm_kernel<0, 0, 0><<<gridE, NT>>>(MB, SDIM, MB, SDIM, MA, GEMM_NULLS);   // MA = G^4
    gemm_kernel<0, 0, 0><<<gridE, NT>>>(MA, SDIM, MA, SDIM, MB, GEMM_NULLS);   // MB = G^8
    gemm_kernel<0, 0, 0><<<gridE, NT>>>(MB, SDIM, MB, SDIM, MA, GEMM_NULLS);   // MA = G^16
    gemm_kernel<0, 0, 0><<<gridE, NT>>>(MA, SDIM, MA, SDIM, MB, GEMM_NULLS);   // MB = G^32

    fill_kernel<<<(SDIM + 255) / 256, 256>>>();
    for (int i = 0; i < PITERS; i++) {
        matvec_kernel<<<SDIM, 256>>>(MB, vec, wvec);
        normalize_kernel<<<1, 256>>>(wvec, vec);
    }
    matvec_kernel<<<SDIM, 256>>>(MB, vec, wvec);
    finalize_kernel<<<1, 256>>>(vec, wvec, alpha);

    // ---- init FISTA state (x0 = y0 = 0) ----
    size_t bytes = (size_t)BATCH * SDIM * sizeof(float);
    cudaMemsetAsync(yth, 0, bytes);
    cudaMemsetAsync(ydl, 0, bytes);
    cudaMemsetAsync(xth, 0, bytes);
    cudaMemsetAsync(xdl, 0, bytes);

    // ---- 16 FISTA iterations, 2 fused kernels each ----
    float t = 1.0f;
    for (int it = 0; it < N_ITER; it++) {
        float tn  = (1.0f + sqrtf(1.0f + 4.0f * t * t)) * 0.5f;
        float mom = (t - 1.0f) / tn;
        t = tn;
        float* op = (it == N_ITER - 1) ? out : nullptr;

        // Z = W * y_theta ; res = Y - src*Z - y_delta ; u = src*res
        gemm_kernel<0, 1, 1><<<gridM, NT>>>(yth, SDIM, W, SDIM, nullptr,
            src, Y, res, u, nullptr, nullptr, nullptr, ydl, nullptr, 0.0f);
        // g = W^T u ; theta/delta soft-threshold + momentum update (+ final output)
        gemm_kernel<0, 0, 2><<<gridM, NT>>>(u, SDIM, W, SDIM, nullptr,
            nullptr, nullptr, res, nullptr, xth, yth, xdl, ydl, op, mom);
    }
}

// round 3
// speedup vs baseline: 1.2949x; 1.2949x over previous
#include <cuda_runtime.h>
#include <math.h>
#include <stdint.h>

#define BATCH   1024
#define SDIM    2048
#define N_ITER  16
#define PITERS  24
#define KCHUNK  32
#define NCHUNK  (SDIM / KCHUNK)    // 64

// ---------------- static device scratch ----------------
__device__ __align__(256) float g_yth[BATCH * SDIM];
__device__ __align__(256) float g_ydl[BATCH * SDIM];
__device__ __align__(256) float g_xth[BATCH * SDIM];
__device__ __align__(256) float g_xdl[BATCH * SDIM];
__device__ __align__(256) float g_u  [BATCH * SDIM];
__device__ __align__(256) float g_res[BATCH * SDIM];
__device__ __align__(256) float g_WT [SDIM * SDIM];
__device__ __align__(256) float g_MA [SDIM * SDIM];
__device__ __align__(256) float g_MB [SDIM * SDIM];
__device__ __align__(256) float g_vec [SDIM];
__device__ __align__(256) float g_wvec[SDIM];
__device__ float g_scal[4];   // [0] = 1/L, [1] = thresh

// SMEM layout per stage (fragment layout, bytes):
//   Ahi [0, 8192)   Alo [8192, 16384)   Bhi [16384, 24576)   Blo [24576, 32768)
#define STAGE_B    32768
#define SMEM_TOTAL (2 * STAGE_B)

static __device__ __forceinline__ uint32_t smem_u32(const void* p) {
    uint32_t a;
    asm("{ .reg .u64 t; cvta.to.shared.u64 t, %1; cvt.u32.u64 %0, t; }" : "=r"(a) : "l"(p));
    return a;
}
static __device__ __forceinline__ void lds128(uint32_t* r, uint32_t a) {
    asm volatile("ld.shared.v4.b32 {%0,%1,%2,%3}, [%4];"
                 : "=r"(r[0]), "=r"(r[1]), "=r"(r[2]), "=r"(r[3]) : "r"(a));
}
static __device__ __forceinline__ void lds64(uint32_t* r, uint32_t a) {
    asm volatile("ld.shared.v2.b32 {%0,%1}, [%2];" : "=r"(r[0]), "=r"(r[1]) : "r"(a));
}
static __device__ __forceinline__ void sts32(uint32_t a, uint32_t v) {
    asm volatile("st.shared.b32 [%0], %1;" :: "r"(a), "r"(v));
}
static __device__ __forceinline__ void mma16816(float* d, const uint32_t* a, const uint32_t* b) {
    asm volatile(
        "mma.sync.aligned.m16n8k16.row.col.f32.bf16.bf16.f32 "
        "{%0,%1,%2,%3}, {%4,%5,%6,%7}, {%8,%9}, {%0,%1,%2,%3};"
        : "+f"(d[0]), "+f"(d[1]), "+f"(d[2]), "+f"(d[3])
        : "r"(a[0]), "r"(a[1]), "r"(a[2]), "r"(a[3]), "r"(b[0]), "r"(b[1]));
}

// split 8 fp32 (one k8 group) into 4 packed bf16x2 hi (truncated) + 4 lo (residual)
static __device__ __forceinline__ void split8(float4 a, float4 b, uint32_t* h, uint32_t* l) {
    uint32_t ux = __float_as_uint(a.x), uy = __float_as_uint(a.y);
    uint32_t uz = __float_as_uint(a.z), uw = __float_as_uint(a.w);
    uint32_t vx = __float_as_uint(b.x), vy = __float_as_uint(b.y);
    uint32_t vz = __float_as_uint(b.z), vw = __float_as_uint(b.w);
    h[0] = __byte_perm(ux, uy, 0x7632);
    h[1] = __byte_perm(uz, uw, 0x7632);
    h[2] = __byte_perm(vx, vy, 0x7632);
    h[3] = __byte_perm(vz, vw, 0x7632);
    float r0 = a.x - __uint_as_float(ux & 0xFFFF0000u);
    float r1 = a.y - __uint_as_float(uy & 0xFFFF0000u);
    float r2 = a.z - __uint_as_float(uz & 0xFFFF0000u);
    float r3 = a.w - __uint_as_float(uw & 0xFFFF0000u);
    float r4 = b.x - __uint_as_float(vx & 0xFFFF0000u);
    float r5 = b.y - __uint_as_float(vy & 0xFFFF0000u);
    float r6 = b.z - __uint_as_float(vz & 0xFFFF0000u);
    float r7 = b.w - __uint_as_float(vw & 0xFFFF0000u);
    asm("cvt.rn.bf16x2.f32 %0, %1, %2;" : "=r"(l[0]) : "f"(r1), "f"(r0));
    asm("cvt.rn.bf16x2.f32 %0, %1, %2;" : "=r"(l[1]) : "f"(r3), "f"(r2));
    asm("cvt.rn.bf16x2.f32 %0, %1, %2;" : "=r"(l[2]) : "f"(r5), "f"(r4));
    asm("cvt.rn.bf16x2.f32 %0, %1, %2;" : "=r"(l[3]) : "f"(r7), "f"(r6));
}

static __device__ __forceinline__ float softthr(float v, float th) {
    float a = fabsf(v) - th;
    return a > 0.0f ? copysignf(a, v) : 0.0f;
}

// ---------------------------------------------------------------------------
// C[m,n] = sum_k A[m,k] * B[n,k], K = 2048. CTA tile 128x128, warp tile 32x64.
// EPI 0: C = acc*scale   EPI 1: res/u epilogue   EPI 2: FISTA update (+out)
// ---------------------------------------------------------------------------
template<int EPI>
__global__ void __launch_bounds__(256)
mma_gemm(const float* __restrict__ A, const float* __restrict__ Bm,
         float* __restrict__ C, float scale,
         const float* __restrict__ src, const float* __restrict__ Yg,
         float* __restrict__ resv, float* __restrict__ uv,
         float* __restrict__ xth, float* __restrict__ yth,
         float* __restrict__ xdl, float* __restrict__ ydl,
         float* __restrict__ outp, float mom)
{
    extern __shared__ char smem[];
    const uint32_t sb = smem_u32(smem);
    const int tid = threadIdx.x;
    const int wid = tid >> 5, lid = tid & 31;
    const int wm = wid & 3, wn = wid >> 2;   // warps 4 x 2 over (M, N)
    const int row0 = blockIdx.y * 128, col0 = blockIdx.x * 128;

    // ---- producer static mapping: item -> (row r, k8-group c8) + STS bases ----
    int rr[2], cc[2];
    uint32_t aSt[2], bSt[2];
#pragma unroll
    for (int it = 0; it < 2; it++) {
        int grp = tid + it * 256;
        int r = grp & 127, c8 = grp >> 7;
        rr[it] = r; cc[it] = c8;
        int kblk = c8 >> 1, half = c8 & 1;
        int mblk = r >> 4, gm = r & 15;
        aSt[it] = sb + (uint32_t)(((mblk * 2 + kblk) << 9) + ((gm & 7) << 6)
                                  + (half * 2 + (gm >> 3)) * 4);
        int nblk = r >> 3, gn = r & 7;
        bSt[it] = sb + 16384u + (uint32_t)(((nblk * 2 + kblk) << 8) + (gn << 5) + half * 4);
    }

    float acc[2][8][4];
#pragma unroll
    for (int i = 0; i < 2; i++)
#pragma unroll
        for (int j = 0; j < 8; j++)
#pragma unroll
            for (int q = 0; q < 4; q++) acc[i][j][q] = 0.0f;

    const float* Ab = A + (size_t)row0 * SDIM;
    const float* Bb = Bm + (size_t)col0 * SDIM;

    float4 pA[2][2], pB[2][2];

#define LDG_CHUNK(kt)                                                          \
    do {                                                                       \
        _Pragma("unroll")                                                      \
        for (int it = 0; it < 2; it++) {                                       \
            const float* pa = Ab + (size_t)rr[it] * SDIM + (kt) + cc[it] * 8;  \
            pA[it][0] = *reinterpret_cast<const float4*>(pa);                  \
            pA[it][1] = *reinterpret_cast<const float4*>(pa + 4);              \
            const float* pb = Bb + (size_t)rr[it] * SDIM + (kt) + cc[it] * 8;  \
            pB[it][0] = *reinterpret_cast<const float4*>(pb);                  \
            pB[it][1] = *reinterpret_cast<const float4*>(pb + 4);              \
        }                                                                      \
    } while (0)

#define STS_CHUNK(stoff)                                                       \
    do {                                                                       \
        _Pragma("unroll")                                                      \
        for (int it = 0; it < 2; it++) {                                       \
            uint32_t h[4], l[4];                                               \
            split8(pA[it][0], pA[it][1], h, l);                                \
            _Pragma("unroll")                                                  \
            for (int j = 0; j < 4; j++) {                                      \
                sts32(aSt[it] + (stoff) + j * 16, h[j]);                       \
                sts32(aSt[it] + (stoff) + 8192u + j * 16, l[j]);               \
            }                                                                  \
            split8(pB[it][0], pB[it][1], h, l);                                \
            _Pragma("unroll")                                                  \
            for (int j = 0; j < 4; j++) {                                      \
                sts32(bSt[it] + (stoff) + j * 8, h[j]);                        \
                sts32(bSt[it] + (stoff) + 8192u + j * 8, l[j]);                \
            }                                                                  \
        }                                                                      \
    } while (0)

    LDG_CHUNK(0);
    STS_CHUNK(0u);
    __syncthreads();

#pragma unroll 1
    for (int c = 0; c < NCHUNK; c++) {
        if (c + 1 < NCHUNK) LDG_CHUNK((c + 1) * KCHUNK);

        const uint32_t s0 = sb + (uint32_t)((c & 1) * STAGE_B);
#pragma unroll
        for (int kb = 0; kb < 2; kb++) {
            uint32_t ah[2][4], al[2][4];
#pragma unroll
            for (int bm = 0; bm < 2; bm++) {
                uint32_t ab = s0 + (uint32_t)((((wm * 2 + bm) * 2 + kb) << 9) + (lid << 4));
                lds128(ah[bm], ab);
                lds128(al[bm], ab + 8192u);
            }
#pragma unroll
            for (int bn = 0; bn < 8; bn++) {
                uint32_t bb = s0 + 16384u + (uint32_t)((((wn * 8 + bn) * 2 + kb) << 8) + (lid << 3));
                uint32_t bh[2], bl[2];
                lds64(bh, bb);
                lds64(bl, bb + 8192u);
#pragma unroll
                for (int bm = 0; bm < 2; bm++) {
                    mma16816(acc[bm][bn], ah[bm], bh);
                    mma16816(acc[bm][bn], ah[bm], bl);
                    mma16816(acc[bm][bn], al[bm], bh);
                }
            }
        }

        if (c + 1 < NCHUNK) STS_CHUNK((uint32_t)(((c + 1) & 1) * STAGE_B));
        __syncthreads();
    }

    // ---- epilogue ----
    const float invL = (EPI == 2) ? g_scal[0] : 0.0f;
    const float th   = (EPI == 2) ? g_scal[1] : 0.0f;
    const int gid = lid >> 2, tig = lid & 3;
#pragma unroll
    for (int bm = 0; bm < 2; bm++) {
#pragma unroll
        for (int bn = 0; bn < 8; bn++) {
            const int n = col0 + wn * 64 + bn * 8 + tig * 2;
#pragma unroll
            for (int hr = 0; hr < 2; hr++) {
                const int m = row0 + wm * 32 + bm * 16 + gid + hr * 8;
                float ax = acc[bm][bn][hr * 2 + 0];
                float ay = acc[bm][bn][hr * 2 + 1];
                const size_t idx = (size_t)m * SDIM + n;
                if (EPI == 0) {
                    float2 o; o.x = ax * scale; o.y = ay * scale;
                    *reinterpret_cast<float2*>(C + idx) = o;
                } else if (EPI == 1) {
                    float2 s  = *reinterpret_cast<const float2*>(src + idx);
                    float2 yv = *reinterpret_cast<const float2*>(Yg + idx);
                    float2 yd = *reinterpret_cast<const float2*>(ydl + idx);
                    float2 r, uu;
                    r.x = yv.x - s.x * ax - yd.x;  uu.x = s.x * r.x;
                    r.y = yv.y - s.y * ay - yd.y;  uu.y = s.y * r.y;
                    *reinterpret_cast<float2*>(resv + idx) = r;
                    *reinterpret_cast<float2*>(uv + idx)   = uu;
                } else {
                    float2 yt = *reinterpret_cast<const float2*>(yth + idx);
                    float2 xt = *reinterpret_cast<const float2*>(xth + idx);
                    float2 xn, yn;
                    xn.x = softthr(yt.x + ax * invL, th);  yn.x = xn.x + mom * (xn.x - xt.x);
                    xn.y = softthr(yt.y + ay * invL, th);  yn.y = xn.y + mom * (xn.y - xt.y);
                    *reinterpret_cast<float2*>(xth + idx) = xn;
                    *reinterpret_cast<float2*>(yth + idx) = yn;
                    float2 rs = *reinterpret_cast<const float2*>(resv + idx);
                    float2 yd = *reinterpret_cast<const float2*>(ydl + idx);
                    float2 xd = *reinterpret_cast<const float2*>(xdl + idx);
                    float2 xnd, ynd;
                    xnd.x = softthr(yd.x + rs.x * invL, th);  ynd.x = xnd.x + mom * (xnd.x - xd.x);
                    xnd.y = softthr(yd.y + rs.y * invL, th);  ynd.y = xnd.y + mom * (xnd.y - xd.y);
                    *reinterpret_cast<float2*>(xdl + idx) = xnd;
                    *reinterpret_cast<float2*>(ydl + idx) = ynd;
                    if (outp) {
                        const size_t ob = (size_t)m * (2 * SDIM) + n;
                        *reinterpret_cast<float2*>(outp + ob)        = xn;
                        *reinterpret_cast<float2*>(outp + ob + SDIM) = xnd;
                    }
                }
            }
        }
    }
}

// ---------------- helper kernels ----------------
__global__ void transpose_kernel(const float* __restrict__ in, float* __restrict__ out) {
    __shared__ float t[32][33];
    int bx = blockIdx.x * 32, by = blockIdx.y * 32;
    int x = bx + threadIdx.x;
#pragma unroll
    for (int i = threadIdx.y; i < 32; i += 8)
        t[i][threadIdx.x] = in[(size_t)(by + i) * SDIM + x];
    __syncthreads();
    int x2 = by + threadIdx.x;
#pragma unroll
    for (int i = threadIdx.y; i < 32; i += 8)
        out[(size_t)(bx + i) * SDIM + x2] = t[threadIdx.x][i];
}

__global__ void fill_kernel() {
    int i = blockIdx.x * blockDim.x + threadIdx.x;
    if (i < SDIM) {
        unsigned h = (unsigned)i * 2654435761u;
        h ^= h >> 13; h *= 2246822519u; h ^= h >> 16;
        g_vec[i] = (float)(h & 0xFFFF) / 65536.0f - 0.5f;
    }
}

__global__ void matvec_kernel(const float* __restrict__ H,
                              const float* __restrict__ x,
                              float* __restrict__ y) {
    int row = blockIdx.x;
    const float* hr = H + (size_t)row * SDIM;
    float s = 0.0f;
    for (int j = threadIdx.x; j < SDIM; j += 256) s += hr[j] * x[j];
#pragma unroll
    for (int o = 16; o > 0; o >>= 1) s += __shfl_xor_sync(0xffffffffu, s, o);
    __shared__ float part[8];
    int w = threadIdx.x >> 5;
    if ((threadIdx.x & 31) == 0) part[w] = s;
    __syncthreads();
    if (threadIdx.x == 0) {
        float t = 0.0f;
#pragma unroll
        for (int k = 0; k < 8; k++) t += part[k];
        y[row] = t;
    }
}

__global__ void normalize_kernel(const float* __restrict__ w, float* __restrict__ v) {
    float ss = 0.0f;
    for (int i = threadIdx.x; i < SDIM; i += 256) { float t = w[i]; ss += t * t; }
#pragma unroll
    for (int o = 16; o > 0; o >>= 1) ss += __shfl_xor_sync(0xffffffffu, ss, o);
    __shared__ float part[8];
    __shared__ float s_inv;
    int wd = threadIdx.x >> 5;
    if ((threadIdx.x & 31) == 0) part[wd] = ss;
    __syncthreads();
    if (threadIdx.x == 0) {
        float t = 0.0f;
        for (int i = 0; i < 8; i++) t += part[i];
        s_inv = rsqrtf(t);
    }
    __syncthreads();
    float inv = s_inv;
    for (int i = threadIdx.x; i < SDIM; i += 256) v[i] = w[i] * inv;
}

// Rayleigh on G'^64 (G' = G/4): L = 4 * lam^(1/64); writes 1/L and thresh.
__global__ void finalize_kernel(const float* __restrict__ v,
                                const float* __restrict__ w,
                                const float* __restrict__ alpha) {
    float num = 0.0f, den = 0.0f;
    for (int i = threadIdx.x; i < SDIM; i += 256) { num += v[i] * w[i]; den += v[i] * v[i]; }
#pragma unroll
    for (int o = 16; o > 0; o >>= 1) {
        num += __shfl_xor_sync(0xffffffffu, num, o);
        den += __shfl_xor_sync(0xffffffffu, den, o);
    }
    __shared__ float pn[8], pd[8];
    int wd = threadIdx.x >> 5;
    if ((threadIdx.x & 31) == 0) { pn[wd] = num; pd[wd] = den; }
    __syncthreads();
    if (threadIdx.x == 0) {
        double n = 0.0, d = 0.0;
        for (int i = 0; i < 8; i++) { n += pn[i]; d += pd[i]; }
        double lam = n / d;
        double L = 4.0 * pow(lam, 1.0 / 64.0);
        g_scal[0] = (float)(1.0 / L);
        g_scal[1] = (float)((double)alpha[0] * 0.5 / L);
    }
}

#define EPI_NULLS nullptr, nullptr, nullptr, nullptr, nullptr, nullptr, nullptr, nullptr, nullptr, 0.0f

extern "C" void kernel_launch(void* const* d_in, const int* in_sizes, int n_in,
                              void* d_out, int out_size) {
    (void)in_sizes; (void)n_in; (void)out_size;
    const float* src   = (const float*)d_in[0];
    const float* Y     = (const float*)d_in[1];
    const float* W     = (const float*)d_in[2];
    const float* alpha = (const float*)d_in[3];
    float* out = (float*)d_out;

    float *yth, *ydl, *xth, *xdl, *u, *res, *WT, *MA, *MB, *vec, *wvec;
    cudaGetSymbolAddress((void**)&yth,  g_yth);
    cudaGetSymbolAddress((void**)&ydl,  g_ydl);
    cudaGetSymbolAddress((void**)&xth,  g_xth);
    cudaGetSymbolAddress((void**)&xdl,  g_xdl);
    cudaGetSymbolAddress((void**)&u,    g_u);
    cudaGetSymbolAddress((void**)&res,  g_res);
    cudaGetSymbolAddress((void**)&WT,   g_WT);
    cudaGetSymbolAddress((void**)&MA,   g_MA);
    cudaGetSymbolAddress((void**)&MB,   g_MB);
    cudaGetSymbolAddress((void**)&vec,  g_vec);
    cudaGetSymbolAddress((void**)&wvec, g_wvec);

    cudaFuncSetAttribute(mma_gemm<0>, cudaFuncAttributeMaxDynamicSharedMemorySize, SMEM_TOTAL);
    cudaFuncSetAttribute(mma_gemm<1>, cudaFuncAttributeMaxDynamicSharedMemorySize, SMEM_TOTAL);
    cudaFuncSetAttribute(mma_gemm<2>, cudaFuncAttributeMaxDynamicSharedMemorySize, SMEM_TOTAL);

    dim3 ge(SDIM / 128, SDIM / 128);   // 16 x 16
    dim3 ga(SDIM / 128, BATCH / 128);  // 16 x 8

    // WT = W^T
    transpose_kernel<<<dim3(64, 64), dim3(32, 8)>>>(W, WT);

    // eigen chain: G' = (W^T W)/4 = WT * WT^T / 4, then 6 squarings -> G'^64 in MA
    mma_gemm<0><<<ge, 256, SMEM_TOTAL>>>(WT, WT, MA, 0.25f, EPI_NULLS);
    mma_gemm<0><<<ge, 256, SMEM_TOTAL>>>(MA, MA, MB, 1.0f, EPI_NULLS);
    mma_gemm<0><<<ge, 256, SMEM_TOTAL>>>(MB, MB, MA, 1.0f, EPI_NULLS);
    mma_gemm<0><<<ge, 256, SMEM_TOTAL>>>(MA, MA, MB, 1.0f, EPI_NULLS);
    mma_gemm<0><<<ge, 256, SMEM_TOTAL>>>(MB, MB, MA, 1.0f, EPI_NULLS);
    mma_gemm<0><<<ge, 256, SMEM_TOTAL>>>(MA, MA, MB, 1.0f, EPI_NULLS);
    mma_gemm<0><<<ge, 256, SMEM_TOTAL>>>(MB, MB, MA, 1.0f, EPI_NULLS);

    // power iteration + Rayleigh on G'^64
    fill_kernel<<<(SDIM + 255) / 256, 256>>>();
    for (int i = 0; i < PITERS; i++) {
        matvec_kernel<<<SDIM, 256>>>(MA, vec, wvec);
        normalize_kernel<<<1, 256>>>(wvec, vec);
    }
    matvec_kernel<<<SDIM, 256>>>(MA, vec, wvec);
    finalize_kernel<<<1, 256>>>(vec, wvec, alpha);

    // FISTA state init (x0 = y0 = 0)
    size_t bytes = (size_t)BATCH * SDIM * sizeof(float);
    cudaMemsetAsync(yth, 0, bytes);
    cudaMemsetAsync(ydl, 0, bytes);
    cudaMemsetAsync(xth, 0, bytes);
    cudaMemsetAsync(xdl, 0, bytes);

    float t = 1.0f;
    for (int it = 0; it < N_ITER; it++) {
        float tn  = (1.0f + sqrtf(1.0f + 4.0f * t * t)) * 0.5f;
        float mom = (t - 1.0f) / tn;
        t = tn;
        float* op = (it == N_ITER - 1) ? out : nullptr;

        // Z = yth * W^T ; res = Y - src*Z - ydl ; u = src*res
        mma_gemm<1><<<ga, 256, SMEM_TOTAL>>>(yth, W, nullptr, 0.0f,
            src, Y, res, u, nullptr, nullptr, nullptr, ydl, nullptr, 0.0f);
        // g = u * WT^T = W^T u ; theta/delta soft-threshold + momentum (+ out)
        mma_gemm<2><<<ga, 256, SMEM_TOTAL>>>(u, WT, nullptr, 0.0f,
            nullptr, nullptr, res, nullptr, xth, yth, xdl, ydl, op, mom);
    }
}